// round 4
// baseline (speedup 1.0000x reference)
#include <cuda_runtime.h>
#include <cstdint>

#define B    16
#define C    96
#define HW   50176
#define HW4  12544
#define KSEL 25088
#define CHUNKS 3
#define CPT  32      // channels per chunk

// Scratch (no allocs allowed).
__device__ float        g_part[CHUNKS * B * HW];     // 9.6 MB partial energies
__device__ float        g_e2[B * HW];                // 3.2 MB combined energy^2
__device__ unsigned int g_hist16[B * 65536];         // 4 MB per-batch hist of key>>16
__device__ unsigned int g_cand[B * HW];              // candidate keys (worst case safe)
__device__ unsigned int g_ccount[B];
__device__ unsigned int g_prefix16[B];
__device__ unsigned int g_remk[B];
__device__ unsigned int g_thresh[B];
__device__ unsigned int g_maskbits[B * HW / 32];     // 100 KB

// ---------------------------------------------------------------------------
// Pass 1: partial energy over 32-channel chunks (HBM roofline). Also zeroes
// the histogram and candidate counters for this replay (runs first in graph).
// ---------------------------------------------------------------------------
__global__ void energy_kernel(const float4* __restrict__ x) {
    int idx = blockIdx.x * blockDim.x + threadIdx.x;      // over CHUNKS*B*HW4
    if (idx < B * 65536 / 4) {
        uint4 z; z.x = z.y = z.z = z.w = 0u;
        reinterpret_cast<uint4*>(g_hist16)[idx] = z;
    }
    if (idx < B) g_ccount[idx] = 0u;
    if (idx >= CHUNKS * B * HW4) return;
    int chunk = idx / (B * HW4);
    int r     = idx - chunk * (B * HW4);
    int b     = r / HW4;
    int p     = r - b * HW4;
    const float4* base = x + (size_t)b * (C * HW4) + (size_t)(chunk * CPT) * HW4 + p;
    float ax = 0.f, ay = 0.f, az = 0.f, aw = 0.f;
#pragma unroll 16
    for (int c = 0; c < CPT; c++) {
        float4 v = __ldcs(base + (size_t)c * HW4);
        ax += v.x * v.x; ay += v.y * v.y; az += v.z * v.z; aw += v.w * v.w;
    }
    float4 o; o.x = ax; o.y = ay; o.z = az; o.w = aw;
    reinterpret_cast<float4*>(g_part)[idx] = o;
}

// ---------------------------------------------------------------------------
// Pass 2 (wide): combine partials -> e2, histogram top-16 bits per batch.
// Warps never straddle batches (HW4 % 32 == 0) so match_any digits are
// batch-consistent. energy2 >= 0 => uint bit order == float order.
// ---------------------------------------------------------------------------
__global__ void combine_hist_kernel() {
    int idx = blockIdx.x * blockDim.x + threadIdx.x;      // over B*HW4 (exact)
    int b = idx / HW4;
    const float4* part = reinterpret_cast<const float4*>(g_part);
    float4 a  = part[idx];
    float4 p1 = part[idx + B * HW4];
    float4 p2 = part[idx + 2 * B * HW4];
    float4 e;
    e.x = a.x + p1.x + p2.x;
    e.y = a.y + p1.y + p2.y;
    e.z = a.z + p1.z + p2.z;
    e.w = a.w + p1.w + p2.w;
    reinterpret_cast<float4*>(g_e2)[idx] = e;
    unsigned int* hist = g_hist16 + ((unsigned)b << 16);
#pragma unroll
    for (int j = 0; j < 4; j++) {
        float f = (j == 0) ? e.x : (j == 1) ? e.y : (j == 2) ? e.z : e.w;
        unsigned int dig = __float_as_uint(f) >> 16;
        unsigned int m = __match_any_sync(0xFFFFFFFFu, dig);
        if ((int)(threadIdx.x & 31) == (__ffs(m) - 1))
            atomicAdd(&hist[dig], (unsigned)__popc(m));
    }
}

// ---------------------------------------------------------------------------
// Pass 3 (narrow): per-batch suffix-scan of the 64K-bin histogram to find the
// bin containing the k-th largest key. One block per batch.
// ---------------------------------------------------------------------------
__global__ void scan16_kernel() {
    int b   = blockIdx.x;
    int tid = threadIdx.x;                                // 0..1023
    const unsigned int* hist = g_hist16 + ((unsigned)b << 16);
    __shared__ unsigned int ss[1024];

    unsigned int s = 0;
    int base = tid * 64;
#pragma unroll 8
    for (int i = 0; i < 64; i++) s += hist[base + i];
    ss[tid] = s;
    __syncthreads();
    for (int off = 1; off < 1024; off <<= 1) {
        unsigned int v = (tid + off < 1024) ? ss[tid + off] : 0u;
        __syncthreads();
        ss[tid] += v;
        __syncthreads();
    }
    unsigned int remk  = KSEL;
    unsigned int below = (tid + 1 < 1024) ? ss[tid + 1] : 0u;  // keys in higher chunks
    if (ss[tid] >= remk && below < remk) {
        unsigned int cum = below;
        for (int bin = base + 63; bin >= base; bin--) {
            unsigned int h = hist[bin];
            if (cum + h >= remk) {
                g_prefix16[b] = (unsigned)bin;
                g_remk[b]     = remk - cum;
                break;
            }
            cum += h;
        }
    }
}

// ---------------------------------------------------------------------------
// Pass 4 (wide): compact keys whose top-16 bits match the selected bin.
// Order nondeterministic; downstream use is a histogram (order-free).
// ---------------------------------------------------------------------------
__global__ void compact_kernel() {
    int idx = blockIdx.x * blockDim.x + threadIdx.x;      // over B*HW4 (exact)
    int b = idx / HW4;
    unsigned int pref = g_prefix16[b];
    uint4 kv = reinterpret_cast<const uint4*>(g_e2)[idx];
#pragma unroll
    for (int j = 0; j < 4; j++) {
        unsigned int key = (j == 0) ? kv.x : (j == 1) ? kv.y : (j == 2) ? kv.z : kv.w;
        if ((key >> 16) == pref) {
            unsigned int pos = atomicAdd(&g_ccount[b], 1u);
            g_cand[b * HW + pos] = key;
        }
    }
}

// ---------------------------------------------------------------------------
// Pass 5 (tiny): exact threshold from candidates via two 8-bit radix passes.
// One block per batch, candidates ~hundreds (L2-resident).
// ---------------------------------------------------------------------------
__global__ void thresh_kernel() {
    int b   = blockIdx.x;
    int tid = threadIdx.x;                                // 0..255
    unsigned int cnt  = g_ccount[b];
    unsigned int remk = g_remk[b];
    unsigned int pref = g_prefix16[b];
    const unsigned int* cand = g_cand + b * HW;

    __shared__ unsigned int hist[256];
    __shared__ unsigned int ss[256];
    __shared__ unsigned int s_binA, s_remkA;

    // Pass A: bits 15:8
    hist[tid] = 0;
    __syncthreads();
    for (unsigned int i = tid; i < cnt; i += 256)
        atomicAdd(&hist[(cand[i] >> 8) & 255u], 1u);
    __syncthreads();
    ss[tid] = hist[tid];
    __syncthreads();
    for (int off = 1; off < 256; off <<= 1) {
        unsigned int v = (tid + off < 256) ? ss[tid + off] : 0u;
        __syncthreads();
        ss[tid] += v;
        __syncthreads();
    }
    {
        unsigned int below = (tid + 1 < 256) ? ss[tid + 1] : 0u;
        if (ss[tid] >= remk && below < remk) {
            s_binA  = (unsigned)tid;
            s_remkA = remk - below;
        }
    }
    __syncthreads();
    unsigned int binA  = s_binA;
    unsigned int remkA = s_remkA;
    __syncthreads();

    // Pass B: bits 7:0 among candidates in binA
    hist[tid] = 0;
    __syncthreads();
    for (unsigned int i = tid; i < cnt; i += 256) {
        unsigned int key = cand[i];
        if (((key >> 8) & 255u) == binA) atomicAdd(&hist[key & 255u], 1u);
    }
    __syncthreads();
    ss[tid] = hist[tid];
    __syncthreads();
    for (int off = 1; off < 256; off <<= 1) {
        unsigned int v = (tid + off < 256) ? ss[tid + off] : 0u;
        __syncthreads();
        ss[tid] += v;
        __syncthreads();
    }
    {
        unsigned int below = (tid + 1 < 256) ? ss[tid + 1] : 0u;
        if (ss[tid] >= remkA && below < remkA)
            g_thresh[b] = (pref << 16) | (binA << 8) | (unsigned)tid;
    }
}

// ---------------------------------------------------------------------------
// Pass 6 (wide): ballot-pack (key >= thresh) into the bitmask.
// ---------------------------------------------------------------------------
__global__ void maskbuild_kernel() {
    int idx = blockIdx.x * blockDim.x + threadIdx.x;      // over B*HW (exact)
    int b = idx / HW;                                     // HW % 32 == 0
    unsigned int key = reinterpret_cast<const unsigned int*>(g_e2)[idx];
    unsigned int t   = g_thresh[b];
    unsigned int bal = __ballot_sync(0xFFFFFFFFu, key >= t);
    if ((threadIdx.x & 31) == 0) g_maskbits[idx >> 5] = bal;
}

// ---------------------------------------------------------------------------
// Pass 7: out = x * mask (HBM roofline).
// ---------------------------------------------------------------------------
__global__ void mask_kernel(const float4* __restrict__ x, float4* __restrict__ out) {
    int t = blockIdx.x * blockDim.x + threadIdx.x;        // over B*C*HW4/2
    if (t >= B * C * HW4 / 2) return;
    int idx = t * 2;
    int b  = idx / (C * HW4);
    int p  = idx % HW4;
    int hw = p * 4;
    unsigned int bits = g_maskbits[((unsigned)(b * HW + hw)) >> 5] >> (hw & 31);
    float4 v0 = __ldcs(x + (size_t)idx);
    float4 v1 = __ldcs(x + (size_t)idx + 1);
    float4 r0, r1;
    r0.x = (bits &   1u) ? v0.x : 0.f;
    r0.y = (bits &   2u) ? v0.y : 0.f;
    r0.z = (bits &   4u) ? v0.z : 0.f;
    r0.w = (bits &   8u) ? v0.w : 0.f;
    r1.x = (bits &  16u) ? v1.x : 0.f;
    r1.y = (bits &  32u) ? v1.y : 0.f;
    r1.z = (bits &  64u) ? v1.z : 0.f;
    r1.w = (bits & 128u) ? v1.w : 0.f;
    __stcs(out + (size_t)idx,     r0);
    __stcs(out + (size_t)idx + 1, r1);
}

extern "C" void kernel_launch(void* const* d_in, const int* in_sizes, int n_in,
                              void* d_out, int out_size) {
    const float* x = (const float*)d_in[0];
    float*     out = (float*)d_out;

    energy_kernel<<<(CHUNKS * B * HW4) / 256, 256>>>((const float4*)x);
    combine_hist_kernel<<<(B * HW4) / 256, 256>>>();
    scan16_kernel<<<B, 1024>>>();
    compact_kernel<<<(B * HW4) / 256, 256>>>();
    thresh_kernel<<<B, 256>>>();
    maskbuild_kernel<<<(B * HW) / 256, 256>>>();
    mask_kernel<<<(B * C * HW4 / 2 + 255) / 256, 256>>>((const float4*)x, (float4*)out);
}

// round 5
// speedup vs baseline: 1.4667x; 1.4667x over previous
#include <cuda_runtime.h>
#include <cstdint>

#define B     16
#define C     96
#define HW    50176
#define HW4   12544
#define KSEL  25088
#define CHUNKS 3
#define CPT   32       // channels per chunk
#define NB11  2048     // radix bins for bits 31:21
#define BPB   49       // blocks per batch in wide e2 kernels (49*256 = HW4)

// Scratch (no allocs allowed).
__device__ float        g_part[CHUNKS * B * HW];   // 9.6 MB partial energies
__device__ float        g_e2[B * HW];              // 3.2 MB combined energy^2
__device__ unsigned int g_hist[B * NB11];          // 128 KB per-batch hist (bits 31:21)
__device__ unsigned int g_cand[B * HW];            // candidate keys (cannot overflow)
__device__ unsigned int g_ccount[B];
__device__ unsigned int g_prefix[B];               // selected 11-bit top prefix
__device__ unsigned int g_remk[B];                 // rank within selected bin
__device__ unsigned int g_thresh[B];               // exact k-th largest key
__device__ unsigned int g_maskbits[B * HW / 32];   // 100 KB

// ---------------------------------------------------------------------------
// Pass 1: partial energy over 32-channel chunks (HBM roofline, measured 47us).
// Also zeroes the global hist + counters for this graph replay (runs first).
// ---------------------------------------------------------------------------
__global__ void energy_kernel(const float4* __restrict__ x) {
    int idx = blockIdx.x * blockDim.x + threadIdx.x;      // over CHUNKS*B*HW4
    if (idx < B * NB11 / 4) {
        uint4 z; z.x = z.y = z.z = z.w = 0u;
        reinterpret_cast<uint4*>(g_hist)[idx] = z;
    }
    if (idx < B) g_ccount[idx] = 0u;
    if (idx >= CHUNKS * B * HW4) return;
    int chunk = idx / (B * HW4);
    int r     = idx - chunk * (B * HW4);
    int b     = r / HW4;
    int p     = r - b * HW4;
    const float4* base = x + (size_t)b * (C * HW4) + (size_t)(chunk * CPT) * HW4 + p;
    float ax = 0.f, ay = 0.f, az = 0.f, aw = 0.f;
#pragma unroll 16
    for (int c = 0; c < CPT; c++) {
        float4 v = __ldcs(base + (size_t)c * HW4);
        ax += v.x * v.x; ay += v.y * v.y; az += v.z * v.z; aw += v.w * v.w;
    }
    float4 o; o.x = ax; o.y = ay; o.z = az; o.w = aw;
    reinterpret_cast<float4*>(g_part)[idx] = o;
}

// ---------------------------------------------------------------------------
// Pass 2 (wide): combine partials -> e2, smem-histogram bits 31:21, merge
// nonzero bins to the per-batch global hist (sparse -> ~200 atomics/block,
// spread over 32K addresses). 1 block = 1024 keys, single batch.
// energy2 >= 0 => uint bit order == float order.
// ---------------------------------------------------------------------------
__global__ void combine_hist_kernel() {
    __shared__ unsigned int hist[NB11];
    int b   = blockIdx.x / BPB;
    int blk = blockIdx.x % BPB;
    int tid = threadIdx.x;
    for (int i = tid; i < NB11; i += 256) hist[i] = 0;
    __syncthreads();

    int idx = b * HW4 + blk * 256 + tid;                  // float4 index
    const float4* part = reinterpret_cast<const float4*>(g_part);
    float4 a  = part[idx];
    float4 p1 = part[idx + B * HW4];
    float4 p2 = part[idx + 2 * B * HW4];
    float4 e;
    e.x = a.x + p1.x + p2.x;
    e.y = a.y + p1.y + p2.y;
    e.z = a.z + p1.z + p2.z;
    e.w = a.w + p1.w + p2.w;
    reinterpret_cast<float4*>(g_e2)[idx] = e;
#pragma unroll
    for (int j = 0; j < 4; j++) {
        float f = (j == 0) ? e.x : (j == 1) ? e.y : (j == 2) ? e.z : e.w;
        unsigned int dig = __float_as_uint(f) >> 21;
        unsigned int m = __match_any_sync(0xFFFFFFFFu, dig);
        if ((int)(tid & 31) == (__ffs(m) - 1))
            atomicAdd(&hist[dig], (unsigned)__popc(m));
    }
    __syncthreads();

    unsigned int* gh = g_hist + b * NB11;
    for (int i = tid; i < NB11; i += 256) {
        unsigned int v = hist[i];
        if (v) atomicAdd(&gh[i], v);
    }
}

// ---------------------------------------------------------------------------
// Pass 3 (narrow, tiny): suffix-scan the 2048-bin hist, pick the bin holding
// the k-th largest key. One block per batch.
// ---------------------------------------------------------------------------
__global__ void scan_kernel() {
    int b   = blockIdx.x;
    int tid = threadIdx.x;                                // 0..1023
    const unsigned int* hist = g_hist + b * NB11;
    __shared__ unsigned int ss[1024];

    unsigned int h0 = hist[2 * tid], h1 = hist[2 * tid + 1];
    ss[tid] = h0 + h1;
    __syncthreads();
    for (int off = 1; off < 1024; off <<= 1) {
        unsigned int v = (tid + off < 1024) ? ss[tid + off] : 0u;
        __syncthreads();
        ss[tid] += v;
        __syncthreads();
    }
    unsigned int remk    = KSEL;
    unsigned int ss_next = (tid + 1 < 1024) ? ss[tid + 1] : 0u;
    unsigned int S1 = ss_next + h1;          // keys with digit >= 2t+1
    unsigned int S0 = S1 + h0;               // keys with digit >= 2t
    unsigned int S2 = ss_next;               // keys with digit >= 2t+2
    if (S1 >= remk && S2 < remk) { g_prefix[b] = 2u * tid + 1u; g_remk[b] = remk - S2; }
    if (S0 >= remk && S1 < remk) { g_prefix[b] = 2u * tid;      g_remk[b] = remk - S1; }
}

// ---------------------------------------------------------------------------
// Pass 4 (wide): compact keys whose top-11 bits match the bin. Block-level
// aggregation: smem offsets + ONE global atomicAdd per block (784 total).
// ---------------------------------------------------------------------------
__global__ void compact_kernel() {
    __shared__ unsigned int s_cnt, s_base;
    int b   = blockIdx.x / BPB;
    int blk = blockIdx.x % BPB;
    int tid = threadIdx.x;
    if (tid == 0) s_cnt = 0u;
    __syncthreads();

    unsigned int pref = g_prefix[b];
    int idx = b * HW4 + blk * 256 + tid;
    uint4 kv = reinterpret_cast<const uint4*>(g_e2)[idx];
    unsigned int mykeys[4];
    int n = 0;
#pragma unroll
    for (int j = 0; j < 4; j++) {
        unsigned int key = (j == 0) ? kv.x : (j == 1) ? kv.y : (j == 2) ? kv.z : kv.w;
        if ((key >> 21) == pref) mykeys[n++] = key;
    }
    unsigned int off = n ? atomicAdd(&s_cnt, (unsigned)n) : 0u;
    __syncthreads();
    if (tid == 0) s_base = atomicAdd(&g_ccount[b], s_cnt);
    __syncthreads();
    unsigned int base = s_base + off;
    for (int i = 0; i < n; i++) g_cand[b * HW + base + i] = mykeys[i];
}

// ---------------------------------------------------------------------------
// Pass 5 (narrow): exact threshold from L2-resident candidates via two smem
// radix passes (bits 20:10 then 9:0). One block per batch, 1024 threads.
// ---------------------------------------------------------------------------
__global__ void thresh_kernel() {
    __shared__ unsigned int hist[NB11];
    __shared__ unsigned int ss[1024];
    __shared__ unsigned int s_binA, s_remkA;
    int b   = blockIdx.x;
    int tid = threadIdx.x;
    unsigned int cnt  = g_ccount[b];
    unsigned int remk = g_remk[b];
    unsigned int pref = g_prefix[b];
    const unsigned int* cand = g_cand + b * HW;
    unsigned int cntp = (cnt + 1023u) & ~1023u;           // converged trip count

    // Pass A: bits 20:10 (2048 bins)
    hist[tid] = 0; hist[tid + 1024] = 0;
    __syncthreads();
    for (unsigned int i = tid; i < cntp; i += 1024) {
        unsigned int dig = 0xFFFFFFFFu;
        if (i < cnt) dig = (cand[i] >> 10) & 2047u;
        unsigned int m = __match_any_sync(0xFFFFFFFFu, dig);
        if (dig != 0xFFFFFFFFu && (int)(tid & 31) == (__ffs(m) - 1))
            atomicAdd(&hist[dig], (unsigned)__popc(m));
    }
    __syncthreads();
    {
        unsigned int h0 = hist[2 * tid], h1 = hist[2 * tid + 1];
        ss[tid] = h0 + h1;
        __syncthreads();
        for (int off = 1; off < 1024; off <<= 1) {
            unsigned int v = (tid + off < 1024) ? ss[tid + off] : 0u;
            __syncthreads();
            ss[tid] += v;
            __syncthreads();
        }
        unsigned int ss_next = (tid + 1 < 1024) ? ss[tid + 1] : 0u;
        unsigned int S1 = ss_next + h1;
        unsigned int S0 = S1 + h0;
        unsigned int S2 = ss_next;
        if (S1 >= remk && S2 < remk) { s_binA = 2u * tid + 1u; s_remkA = remk - S2; }
        if (S0 >= remk && S1 < remk) { s_binA = 2u * tid;      s_remkA = remk - S1; }
    }
    __syncthreads();
    unsigned int binA  = s_binA;
    unsigned int remkA = s_remkA;
    __syncthreads();

    // Pass B: bits 9:0 (1024 bins) among candidates in binA
    hist[tid] = 0;
    __syncthreads();
    for (unsigned int i = tid; i < cntp; i += 1024) {
        unsigned int dig = 0xFFFFFFFFu;
        if (i < cnt) {
            unsigned int key = cand[i];
            if (((key >> 10) & 2047u) == binA) dig = key & 1023u;
        }
        unsigned int m = __match_any_sync(0xFFFFFFFFu, dig);
        if (dig != 0xFFFFFFFFu && (int)(tid & 31) == (__ffs(m) - 1))
            atomicAdd(&hist[dig], (unsigned)__popc(m));
    }
    __syncthreads();
    {
        ss[tid] = hist[tid];
        __syncthreads();
        for (int off = 1; off < 1024; off <<= 1) {
            unsigned int v = (tid + off < 1024) ? ss[tid + off] : 0u;
            __syncthreads();
            ss[tid] += v;
            __syncthreads();
        }
        unsigned int below = (tid + 1 < 1024) ? ss[tid + 1] : 0u;
        if (ss[tid] >= remkA && below < remkA)
            g_thresh[b] = (pref << 21) | (binA << 10) | (unsigned)tid;
    }
}

// ---------------------------------------------------------------------------
// Pass 6 (wide): ballot-pack (key >= thresh) into the bitmask (e2 in L2).
// ---------------------------------------------------------------------------
__global__ void maskbuild_kernel() {
    int idx = blockIdx.x * blockDim.x + threadIdx.x;      // over B*HW (exact)
    int b = idx / HW;                                     // HW % 32 == 0
    unsigned int key = reinterpret_cast<const unsigned int*>(g_e2)[idx];
    unsigned int t   = g_thresh[b];
    unsigned int bal = __ballot_sync(0xFFFFFFFFu, key >= t);
    if ((threadIdx.x & 31) == 0) g_maskbits[idx >> 5] = bal;
}

// ---------------------------------------------------------------------------
// Pass 7: out = x * mask (HBM roofline, measured ~90us).
// ---------------------------------------------------------------------------
__global__ void mask_kernel(const float4* __restrict__ x, float4* __restrict__ out) {
    int t = blockIdx.x * blockDim.x + threadIdx.x;        // over B*C*HW4/2
    if (t >= B * C * HW4 / 2) return;
    int idx = t * 2;
    int b  = idx / (C * HW4);
    int p  = idx % HW4;
    int hw = p * 4;
    unsigned int bits = g_maskbits[((unsigned)(b * HW + hw)) >> 5] >> (hw & 31);
    float4 v0 = __ldcs(x + (size_t)idx);
    float4 v1 = __ldcs(x + (size_t)idx + 1);
    float4 r0, r1;
    r0.x = (bits &   1u) ? v0.x : 0.f;
    r0.y = (bits &   2u) ? v0.y : 0.f;
    r0.z = (bits &   4u) ? v0.z : 0.f;
    r0.w = (bits &   8u) ? v0.w : 0.f;
    r1.x = (bits &  16u) ? v1.x : 0.f;
    r1.y = (bits &  32u) ? v1.y : 0.f;
    r1.z = (bits &  64u) ? v1.z : 0.f;
    r1.w = (bits & 128u) ? v1.w : 0.f;
    __stcs(out + (size_t)idx,     r0);
    __stcs(out + (size_t)idx + 1, r1);
}

extern "C" void kernel_launch(void* const* d_in, const int* in_sizes, int n_in,
                              void* d_out, int out_size) {
    const float* x = (const float*)d_in[0];
    float*     out = (float*)d_out;

    energy_kernel<<<(CHUNKS * B * HW4) / 256, 256>>>((const float4*)x);
    combine_hist_kernel<<<B * BPB, 256>>>();
    scan_kernel<<<B, 1024>>>();
    compact_kernel<<<B * BPB, 256>>>();
    thresh_kernel<<<B, 1024>>>();
    maskbuild_kernel<<<(B * HW) / 256, 256>>>();
    mask_kernel<<<(B * C * HW4 / 2 + 255) / 256, 256>>>((const float4*)x, (float4*)out);
}